// round 1
// baseline (speedup 1.0000x reference)
#include <cuda_runtime.h>

// Problem: out[m,e,k] = sum_n A[m,n] * W[e,n,k]
// A: [8192, 1024] f32 row-major
// W: [64, 1024, 32] f32 (k contiguous)
// out: [8192, 64, 32] f32 -> flattened [8192, 2048] with col = e*32+k
// => SGEMM: C[8192, 2048] = A[8192,1024] * B[1024,2048], B[n, e*32+k] = W[e,n,k]

#define M_DIM 8192
#define N_RED 1024
#define E_DIM 64
#define K_DIM 32
#define NOUT  2048

#define BM 128
#define BN 64
#define BK 16
#define TM 8
#define TN 4
#define NTHREADS 256
#define AS_STRIDE (BM + 4)   // 132 floats -> 528 B, multiple of 16B: keeps LDS.128 alignment

__global__ __launch_bounds__(NTHREADS, 2)
void serial_expert_sgemm(const float* __restrict__ A,
                         const float* __restrict__ W,
                         float* __restrict__ out)
{
    __shared__ float As[2][BK][AS_STRIDE];
    __shared__ float Bs[2][BK][BN];

    const int tid = threadIdx.x;
    const int colBase = blockIdx.x * BN;   // over NOUT
    const int rowBase = blockIdx.y * BM;   // over M

    const int tx = tid & 15;               // 16 cols of threads
    const int ty = tid >> 4;               // 16 rows of threads

    // ---- A global-load mapping: 128x16 tile = 512 float4, 2 per thread ----
    const int a_row0 = tid >> 2;           // 0..63
    const int a_kq   = (tid & 3) * 4;      // k offset within BK: 0,4,8,12
    const int a_row1 = a_row0 + 64;

    // ---- B global-load mapping: 16x64 tile = 256 float4, 1 per thread ----
    const int b_n   = tid >> 4;            // 0..15 (row within BK)
    const int b_c4  = tid & 15;            // 16 float4 across 64 cols
    const int b_col = colBase + b_c4 * 4;  // global output column
    const int b_e   = b_col >> 5;          // expert index
    const int b_k   = b_col & 31;          // k within expert (4-aligned, stays in one expert)

    const float* Abase = A + (size_t)rowBase * N_RED;

    float acc[TM][TN];
    #pragma unroll
    for (int i = 0; i < TM; i++)
        #pragma unroll
        for (int j = 0; j < TN; j++) acc[i][j] = 0.0f;

    float4 a_r0, a_r1, b_r;

    // ---------------- load tile 0 ----------------
    {
        const float* ap = Abase + 0 * BK;
        a_r0 = *(const float4*)(ap + (size_t)a_row0 * N_RED + a_kq);
        a_r1 = *(const float4*)(ap + (size_t)a_row1 * N_RED + a_kq);
        const int n = 0 * BK + b_n;
        b_r = *(const float4*)(W + ((size_t)b_e * N_RED + n) * K_DIM + b_k);
    }
    // store tile 0 into buffer 0 (A transposed)
    As[0][a_kq + 0][a_row0] = a_r0.x;
    As[0][a_kq + 1][a_row0] = a_r0.y;
    As[0][a_kq + 2][a_row0] = a_r0.z;
    As[0][a_kq + 3][a_row0] = a_r0.w;
    As[0][a_kq + 0][a_row1] = a_r1.x;
    As[0][a_kq + 1][a_row1] = a_r1.y;
    As[0][a_kq + 2][a_row1] = a_r1.z;
    As[0][a_kq + 3][a_row1] = a_r1.w;
    *(float4*)&Bs[0][b_n][b_c4 * 4] = b_r;
    __syncthreads();

    const int NT = N_RED / BK;   // 64
    int buf = 0;

    for (int kt = 0; kt < NT; kt++) {
        // prefetch next tile into registers
        if (kt + 1 < NT) {
            const float* ap = Abase + (kt + 1) * BK;
            a_r0 = *(const float4*)(ap + (size_t)a_row0 * N_RED + a_kq);
            a_r1 = *(const float4*)(ap + (size_t)a_row1 * N_RED + a_kq);
            const int n = (kt + 1) * BK + b_n;
            b_r = *(const float4*)(W + ((size_t)b_e * N_RED + n) * K_DIM + b_k);
        }

        // compute from current buffer
        #pragma unroll
        for (int k = 0; k < BK; k++) {
            float4 af0 = *(const float4*)&As[buf][k][ty * TM + 0];
            float4 af1 = *(const float4*)&As[buf][k][ty * TM + 4];
            float4 bf  = *(const float4*)&Bs[buf][k][tx * TN];
            float a0[TM] = {af0.x, af0.y, af0.z, af0.w, af1.x, af1.y, af1.z, af1.w};
            float b0[TN] = {bf.x, bf.y, bf.z, bf.w};
            #pragma unroll
            for (int i = 0; i < TM; i++)
                #pragma unroll
                for (int j = 0; j < TN; j++)
                    acc[i][j] = fmaf(a0[i], b0[j], acc[i][j]);
        }

        // store prefetched tile into the other buffer
        if (kt + 1 < NT) {
            const int nb = buf ^ 1;
            As[nb][a_kq + 0][a_row0] = a_r0.x;
            As[nb][a_kq + 1][a_row0] = a_r0.y;
            As[nb][a_kq + 2][a_row0] = a_r0.z;
            As[nb][a_kq + 3][a_row0] = a_r0.w;
            As[nb][a_kq + 0][a_row1] = a_r1.x;
            As[nb][a_kq + 1][a_row1] = a_r1.y;
            As[nb][a_kq + 2][a_row1] = a_r1.z;
            As[nb][a_kq + 3][a_row1] = a_r1.w;
            *(float4*)&Bs[nb][b_n][b_c4 * 4] = b_r;
            __syncthreads();
            buf = nb;
        }
    }

    // ---------------- epilogue ----------------
    // out flattened: out[m * 2048 + col], col = colBase + tx*TN + j
    // tx*TN is 4-aligned and each 4-col group stays within one expert (32 | colBase).
    #pragma unroll
    for (int i = 0; i < TM; i++) {
        const int m = rowBase + ty * TM + i;
        float4 v = make_float4(acc[i][0], acc[i][1], acc[i][2], acc[i][3]);
        *(float4*)(out + (size_t)m * NOUT + colBase + tx * TN) = v;
    }
}

extern "C" void kernel_launch(void* const* d_in, const int* in_sizes, int n_in,
                              void* d_out, int out_size)
{
    const float* A = (const float*)d_in[0];
    const float* W = (const float*)d_in[1];
    float* out = (float*)d_out;

    dim3 grid(NOUT / BN, M_DIM / BM);   // (32, 64)
    dim3 block(NTHREADS);
    serial_expert_sgemm<<<grid, block>>>(A, W, out);
}

// round 3
// speedup vs baseline: 2.8827x; 2.8827x over previous
#include <cuda_runtime.h>
#include <cstdint>

// out[m, e*32+k] = sum_n A[m,n] * W[e,n,k]
// => C[8192,2048] = A[8192,1024] x B[1024,2048], B[n, e*32+k] = W[e,n,k]
// Legacy-PTX tensor path (base sm_103 target): mma.sync.m16n8k8 tf32.
// Both operands pre-rounded to tf32 (cvt.rna) in prep kernels.

#define M_DIM 8192
#define KR    1024
#define NOUT  2048
#define E_DIM 64

#define BM 128
#define BN 256
#define BK 32
#define STAGES 3
#define KTILES (KR / BK)                 // 32

#define A_STAGE (BM * BK * 4)            // 16 KB
#define B_STAGE (BN * BK * 4)            // 32 KB
#define STAGE_BYTES (A_STAGE + B_STAGE)  // 48 KB
#define SMEM_TOTAL (STAGES * STAGE_BYTES)// 144 KB

__device__ float g_At[(size_t)M_DIM * KR];   // 32 MB: A rounded to tf32
__device__ float g_Bt[(size_t)NOUT * KR];    // 8 MB: W transposed+rounded, [col][n]

// ---------------- helpers ----------------
__device__ __forceinline__ uint32_t smem_u32(const void* p) {
    uint32_t a;
    asm("{ .reg .u64 t; cvta.to.shared.u64 t, %1; cvt.u32.u64 %0, t; }" : "=r"(a) : "l"(p));
    return a;
}
__device__ __forceinline__ float tf32_rna(float x) {
    float y; asm("cvt.rna.tf32.f32 %0, %1;" : "=f"(y) : "f"(x)); return y;
}
__device__ __forceinline__ void cp16(uint32_t dst, const void* src) {
    asm volatile("cp.async.cg.shared.global [%0], [%1], 16;" :: "r"(dst), "l"(src) : "memory");
}
#define CP_COMMIT() asm volatile("cp.async.commit_group;" ::: "memory")
#define CP_WAIT1()  asm volatile("cp.async.wait_group 1;" ::: "memory")

__device__ __forceinline__ void ldsm4(uint32_t* r, uint32_t addr) {
    asm volatile("ldmatrix.sync.aligned.m8n8.x4.shared.b16 {%0,%1,%2,%3}, [%4];"
                 : "=r"(r[0]), "=r"(r[1]), "=r"(r[2]), "=r"(r[3]) : "r"(addr));
}
__device__ __forceinline__ void mma8(float* c, const uint32_t* a, uint32_t b0, uint32_t b1) {
    asm volatile("mma.sync.aligned.m16n8k8.row.col.f32.tf32.tf32.f32 "
                 "{%0,%1,%2,%3}, {%4,%5,%6,%7}, {%8,%9}, {%0,%1,%2,%3};"
                 : "+f"(c[0]), "+f"(c[1]), "+f"(c[2]), "+f"(c[3])
                 : "r"(a[0]), "r"(a[1]), "r"(a[2]), "r"(a[3]), "r"(b0), "r"(b1));
}
// swizzled byte offset for K-major tile, 128B rows: row r, 16B chunk c
__device__ __forceinline__ uint32_t swoff(int r, int c) {
    return (uint32_t)(r * 128 + ((c ^ (r & 7)) << 4));
}

// ---------------- prep kernels ----------------
__global__ void round_A(const float* __restrict__ A) {
    const size_t i = ((size_t)blockIdx.x * blockDim.x + threadIdx.x) * 4;
    float4 v = *(const float4*)(A + i);
    v.x = tf32_rna(v.x); v.y = tf32_rna(v.y); v.z = tf32_rna(v.z); v.w = tf32_rna(v.w);
    *(float4*)(g_At + i) = v;
}

__global__ void transpose_round_W(const float* __restrict__ W) {
    __shared__ float t[32][33];
    const int e = blockIdx.y;
    const int n0 = blockIdx.x * 32;
    const int tid = threadIdx.x;            // 256
    {
        const int i = tid >> 3, k4 = (tid & 7) * 4;
        float4 v = *(const float4*)(W + ((size_t)e * KR + n0 + i) * 32 + k4);
        t[i][k4 + 0] = tf32_rna(v.x);
        t[i][k4 + 1] = tf32_rna(v.y);
        t[i][k4 + 2] = tf32_rna(v.z);
        t[i][k4 + 3] = tf32_rna(v.w);
    }
    __syncthreads();
    {
        const int k = tid >> 3, j4 = (tid & 7) * 4;
        float4 o = make_float4(t[j4 + 0][k], t[j4 + 1][k], t[j4 + 2][k], t[j4 + 3][k]);
        *(float4*)(g_Bt + ((size_t)(e * 32 + k)) * KR + n0 + j4) = o;
    }
}

// ---------------- main GEMM ----------------
__global__ __launch_bounds__(256, 1)
void gemm_tf32_mma(float* __restrict__ out) {
    extern __shared__ char smem[];
    const uint32_t sb = smem_u32(smem);
    const int tid  = threadIdx.x;
    const int lane = tid & 31;
    const int wid  = tid >> 5;
    const int warp_m = wid & 1;     // 2 warps over M  -> 64 rows each
    const int warp_n = wid >> 1;    // 4 warps over N  -> 64 cols each
    const int rowBase = blockIdx.y * BM;
    const int colBase = blockIdx.x * BN;

    const float* gA = g_At + (size_t)rowBase * KR;
    const float* gB = g_Bt + (size_t)colBase * KR;

    // ---- cp.async tile loader ----
    auto load_tile = [&](int stage, int kt) {
        const uint32_t abase = sb + stage * STAGE_BYTES;
        const uint32_t bbase = abase + A_STAGE;
        #pragma unroll
        for (int i = 0; i < 4; i++) {             // A: 128 rows x 8 chunks
            const int lin = i * 256 + tid;
            const int r = lin >> 3, c = lin & 7;
            cp16(abase + swoff(r, c), gA + (size_t)r * KR + kt * BK + c * 4);
        }
        #pragma unroll
        for (int i = 0; i < 8; i++) {             // B: 256 rows x 8 chunks
            const int lin = i * 256 + tid;
            const int r = lin >> 3, c = lin & 7;
            cp16(bbase + swoff(r, c), gB + (size_t)r * KR + kt * BK + c * 4);
        }
    };

    // ---- per-lane ldmatrix row offsets ----
    const int lrow  = ((lane >> 3) & 1) * 8 + (lane & 7);  // row within 16-row frag
    const int lxor  = lane & 7;                             // swizzle xor
    const int lhalf = lane >> 4;                            // chunk +0 / +1
    uint32_t aRow[4], bRow[4];
    #pragma unroll
    for (int mi = 0; mi < 4; mi++) aRow[mi] = (uint32_t)((warp_m * 64 + mi * 16 + lrow) * 128);
    #pragma unroll
    for (int nb = 0; nb < 4; nb++) bRow[nb] = (uint32_t)((warp_n * 64 + nb * 16 + lrow) * 128);

    float acc[4][8][4];
    #pragma unroll
    for (int mi = 0; mi < 4; mi++)
        #pragma unroll
        for (int ni = 0; ni < 8; ni++)
            #pragma unroll
            for (int q = 0; q < 4; q++) acc[mi][ni][q] = 0.0f;

    // ---- pipeline prologue ----
    load_tile(0, 0); CP_COMMIT();
    load_tile(1, 1); CP_COMMIT();

    for (int kt = 0; kt < KTILES; kt++) {
        CP_WAIT1();
        __syncthreads();

        // prefetch kt+2 (empty commit keeps group counting uniform)
        if (kt + 2 < KTILES) load_tile((kt + 2) % STAGES, kt + 2);
        CP_COMMIT();

        const uint32_t abase = sb + (kt % STAGES) * STAGE_BYTES;
        const uint32_t bbase = abase + A_STAGE;

        #pragma unroll
        for (int ks = 0; ks < 4; ks++) {
            const int chunk = ks * 2 + lhalf;
            const uint32_t coff = (uint32_t)((chunk ^ lxor) << 4);

            uint32_t a[4][4];
            #pragma unroll
            for (int mi = 0; mi < 4; mi++) ldsm4(a[mi], abase + aRow[mi] + coff);
            uint32_t b[4][4];
            #pragma unroll
            for (int nb = 0; nb < 4; nb++) ldsm4(b[nb], bbase + bRow[nb] + coff);

            #pragma unroll
            for (int mi = 0; mi < 4; mi++)
                #pragma unroll
                for (int nb = 0; nb < 4; nb++) {
                    mma8(acc[mi][nb * 2 + 0], a[mi], b[nb][0], b[nb][2]);
                    mma8(acc[mi][nb * 2 + 1], a[mi], b[nb][1], b[nb][3]);
                }
        }
    }

    // ---- epilogue: direct stores (float2 per frag row) ----
    const int g = lane >> 2, t = lane & 3;
    #pragma unroll
    for (int mi = 0; mi < 4; mi++) {
        const int r0 = rowBase + warp_m * 64 + mi * 16 + g;
        #pragma unroll
        for (int ni = 0; ni < 8; ni++) {
            const int col = colBase + warp_n * 64 + ni * 8 + t * 2;
            *(float2*)(out + (size_t)r0 * NOUT + col) =
                make_float2(acc[mi][ni][0], acc[mi][ni][1]);
            *(float2*)(out + (size_t)(r0 + 8) * NOUT + col) =
                make_float2(acc[mi][ni][2], acc[mi][ni][3]);
        }
    }
}

extern "C" void kernel_launch(void* const* d_in, const int* in_sizes, int n_in,
                              void* d_out, int out_size)
{
    const float* A = (const float*)d_in[0];
    const float* W = (const float*)d_in[1];
    float* out = (float*)d_out;

    cudaFuncSetAttribute(gemm_tf32_mma, cudaFuncAttributeMaxDynamicSharedMemorySize, SMEM_TOTAL);

    round_A<<<M_DIM * KR / (256 * 4), 256>>>(A);
    transpose_round_W<<<dim3(KR / 32, E_DIM), 256>>>(W);
    gemm_tf32_mma<<<dim3(NOUT / BN, M_DIM / BM), 256, SMEM_TOTAL>>>(out);
}

// round 4
// speedup vs baseline: 3.1101x; 1.0789x over previous
#include <cuda_runtime.h>
#include <cstdint>

// out[m, e*32+k] = sum_n A[m,n] * W[e,n,k]
// => C[8192,2048] = A[8192,1024] x B[1024,2048], B[n, e*32+k] = W[e,n,k]
// Legacy-PTX tensor path (base sm_103 target): mma.sync.m16n8k8 tf32.
// A consumed as raw f32 (HW tf32 truncation); W pre-rounded (cvt.rna) + transposed.

#define M_DIM 8192
#define KR    1024
#define NOUT  2048
#define E_DIM 64

#define BM 128
#define BN 256
#define BK 32
#define STAGES 4
#define KTILES (KR / BK)                 // 32

#define A_STAGE (BM * BK * 4)            // 16 KB
#define B_STAGE (BN * BK * 4)            // 32 KB
#define STAGE_BYTES (A_STAGE + B_STAGE)  // 48 KB
#define SMEM_TOTAL (STAGES * STAGE_BYTES)// 192 KB

__device__ float g_Bt[(size_t)NOUT * KR];    // 8 MB: W transposed+rounded, [col][n]

// ---------------- helpers ----------------
__device__ __forceinline__ uint32_t smem_u32(const void* p) {
    uint32_t a;
    asm("{ .reg .u64 t; cvta.to.shared.u64 t, %1; cvt.u32.u64 %0, t; }" : "=r"(a) : "l"(p));
    return a;
}
__device__ __forceinline__ float tf32_rna(float x) {
    float y; asm("cvt.rna.tf32.f32 %0, %1;" : "=f"(y) : "f"(x)); return y;
}
__device__ __forceinline__ void cp16(uint32_t dst, const void* src) {
    asm volatile("cp.async.cg.shared.global [%0], [%1], 16;" :: "r"(dst), "l"(src) : "memory");
}
#define CP_COMMIT() asm volatile("cp.async.commit_group;" ::: "memory")
#define CP_WAIT2()  asm volatile("cp.async.wait_group 2;" ::: "memory")

__device__ __forceinline__ void ldsm4(uint32_t* r, uint32_t addr) {
    asm volatile("ldmatrix.sync.aligned.m8n8.x4.shared.b16 {%0,%1,%2,%3}, [%4];"
                 : "=r"(r[0]), "=r"(r[1]), "=r"(r[2]), "=r"(r[3]) : "r"(addr));
}
__device__ __forceinline__ void mma8(float* c, const uint32_t* a, uint32_t b0, uint32_t b1) {
    asm volatile("mma.sync.aligned.m16n8k8.row.col.f32.tf32.tf32.f32 "
                 "{%0,%1,%2,%3}, {%4,%5,%6,%7}, {%8,%9}, {%0,%1,%2,%3};"
                 : "+f"(c[0]), "+f"(c[1]), "+f"(c[2]), "+f"(c[3])
                 : "r"(a[0]), "r"(a[1]), "r"(a[2]), "r"(a[3]), "r"(b0), "r"(b1));
}
// swizzled byte offset for K-major tile, 128B rows: row r, 16B chunk c
__device__ __forceinline__ uint32_t swoff(int r, int c) {
    return (uint32_t)(r * 128 + ((c ^ (r & 7)) << 4));
}

// ---------------- prep kernel ----------------
__global__ void transpose_round_W(const float* __restrict__ W) {
    __shared__ float t[32][33];
    const int e = blockIdx.y;
    const int n0 = blockIdx.x * 32;
    const int tid = threadIdx.x;            // 256
    {
        const int i = tid >> 3, k4 = (tid & 7) * 4;
        float4 v = *(const float4*)(W + ((size_t)e * KR + n0 + i) * 32 + k4);
        t[i][k4 + 0] = tf32_rna(v.x);
        t[i][k4 + 1] = tf32_rna(v.y);
        t[i][k4 + 2] = tf32_rna(v.z);
        t[i][k4 + 3] = tf32_rna(v.w);
    }
    __syncthreads();
    {
        const int k = tid >> 3, j4 = (tid & 7) * 4;
        float4 o = make_float4(t[j4 + 0][k], t[j4 + 1][k], t[j4 + 2][k], t[j4 + 3][k]);
        *(float4*)(g_Bt + ((size_t)(e * 32 + k)) * KR + n0 + j4) = o;
    }
}

// ---------------- main GEMM ----------------
__global__ __launch_bounds__(256, 1)
void gemm_tf32_mma(const float* __restrict__ A, float* __restrict__ out) {
    extern __shared__ char smem[];
    const uint32_t sb = smem_u32(smem);
    const int tid  = threadIdx.x;
    const int lane = tid & 31;
    const int wid  = tid >> 5;
    const int warp_m = wid & 1;     // 2 warps over M  -> 64 rows each
    const int warp_n = wid >> 1;    // 4 warps over N  -> 64 cols each
    const int rowBase = blockIdx.y * BM;
    const int colBase = blockIdx.x * BN;

    const float* gA = A + (size_t)rowBase * KR;
    const float* gB = g_Bt + (size_t)colBase * KR;

    // ---- cp.async tile loader ----
    auto load_tile = [&](int stage, int kt) {
        const uint32_t abase = sb + stage * STAGE_BYTES;
        const uint32_t bbase = abase + A_STAGE;
        #pragma unroll
        for (int i = 0; i < 4; i++) {             // A: 128 rows x 8 chunks
            const int lin = i * 256 + tid;
            const int r = lin >> 3, c = lin & 7;
            cp16(abase + swoff(r, c), gA + (size_t)r * KR + kt * BK + c * 4);
        }
        #pragma unroll
        for (int i = 0; i < 8; i++) {             // B: 256 rows x 8 chunks
            const int lin = i * 256 + tid;
            const int r = lin >> 3, c = lin & 7;
            cp16(bbase + swoff(r, c), gB + (size_t)r * KR + kt * BK + c * 4);
        }
    };

    // ---- per-lane ldmatrix row offsets ----
    const int lrow  = ((lane >> 3) & 1) * 8 + (lane & 7);  // row within 16-row frag
    const int lxor  = lane & 7;                             // swizzle xor
    const int lhalf = lane >> 4;                            // chunk +0 / +1
    uint32_t aRow[4], bRow[4];
    #pragma unroll
    for (int mi = 0; mi < 4; mi++) aRow[mi] = (uint32_t)((warp_m * 64 + mi * 16 + lrow) * 128);
    #pragma unroll
    for (int nb = 0; nb < 4; nb++) bRow[nb] = (uint32_t)((warp_n * 64 + nb * 16 + lrow) * 128);

    float acc[4][8][4];
    #pragma unroll
    for (int mi = 0; mi < 4; mi++)
        #pragma unroll
        for (int ni = 0; ni < 8; ni++)
            #pragma unroll
            for (int q = 0; q < 4; q++) acc[mi][ni][q] = 0.0f;

    // ---- pipeline prologue: fill 3 stages ----
    load_tile(0, 0); CP_COMMIT();
    load_tile(1, 1); CP_COMMIT();
    load_tile(2, 2); CP_COMMIT();

    for (int kt = 0; kt < KTILES; kt++) {
        CP_WAIT2();                 // group kt landed (kt+1..kt+3 may be in flight)
        __syncthreads();

        // prefetch kt+3 (empty commit keeps group counting uniform)
        if (kt + 3 < KTILES) load_tile((kt + 3) % STAGES, kt + 3);
        CP_COMMIT();

        const uint32_t abase = sb + (kt % STAGES) * STAGE_BYTES;
        const uint32_t bbase = abase + A_STAGE;

        #pragma unroll
        for (int ks = 0; ks < 4; ks++) {
            const int chunk = ks * 2 + lhalf;
            const uint32_t coff = (uint32_t)((chunk ^ lxor) << 4);

            uint32_t a[4][4];
            #pragma unroll
            for (int mi = 0; mi < 4; mi++) ldsm4(a[mi], abase + aRow[mi] + coff);
            uint32_t b[4][4];
            #pragma unroll
            for (int nb = 0; nb < 4; nb++) ldsm4(b[nb], bbase + bRow[nb] + coff);

            #pragma unroll
            for (int mi = 0; mi < 4; mi++)
                #pragma unroll
                for (int nb = 0; nb < 4; nb++) {
                    mma8(acc[mi][nb * 2 + 0], a[mi], b[nb][0], b[nb][2]);
                    mma8(acc[mi][nb * 2 + 1], a[mi], b[nb][1], b[nb][3]);
                }
        }
    }

    // ---- epilogue: direct stores (float2 per frag row) ----
    const int g = lane >> 2, t = lane & 3;
    #pragma unroll
    for (int mi = 0; mi < 4; mi++) {
        const int r0 = rowBase + warp_m * 64 + mi * 16 + g;
        #pragma unroll
        for (int ni = 0; ni < 8; ni++) {
            const int col = colBase + warp_n * 64 + ni * 8 + t * 2;
            *(float2*)(out + (size_t)r0 * NOUT + col) =
                make_float2(acc[mi][ni][0], acc[mi][ni][1]);
            *(float2*)(out + (size_t)(r0 + 8) * NOUT + col) =
                make_float2(acc[mi][ni][2], acc[mi][ni][3]);
        }
    }
}

extern "C" void kernel_launch(void* const* d_in, const int* in_sizes, int n_in,
                              void* d_out, int out_size)
{
    const float* A = (const float*)d_in[0];
    const float* W = (const float*)d_in[1];
    float* out = (float*)d_out;

    cudaFuncSetAttribute(gemm_tf32_mma, cudaFuncAttributeMaxDynamicSharedMemorySize, SMEM_TOTAL);

    transpose_round_W<<<dim3(KR / 32, E_DIM), 256>>>(W);
    gemm_tf32_mma<<<dim3(NOUT / BN, M_DIM / BM), 256, SMEM_TOTAL>>>(A, out);
}

// round 5
// speedup vs baseline: 3.5681x; 1.1472x over previous
#include <cuda_runtime.h>
#include <cstdint>

// out[m, e*32+k] = sum_n A[m,n] * W[e,n,k]
// => C[8192,2048] = A[8192,1024] x B[1024,2048], B[n, e*32+k] = W[e,n,k]
// mma.sync.m16n8k8 tf32 (base-target tensor path).
// A consumed raw f32 (HW tf32 truncation); W pre-rounded (cvt.rna) + transposed.
// R5: 128x128 tiles, 3 stages, 2 CTAs/SM for latency hiding.

#define M_DIM 8192
#define KR    1024
#define NOUT  2048
#define E_DIM 64

#define BM 128
#define BN 128
#define BK 32
#define STAGES 3
#define KTILES (KR / BK)                 // 32

#define A_STAGE (BM * BK * 4)            // 16 KB
#define B_STAGE (BN * BK * 4)            // 16 KB
#define STAGE_BYTES (A_STAGE + B_STAGE)  // 32 KB
#define SMEM_TOTAL (STAGES * STAGE_BYTES)// 96 KB -> 2 CTAs/SM

__device__ float g_Bt[(size_t)NOUT * KR];    // 8 MB: W transposed+rounded, [col][n]

// ---------------- helpers ----------------
__device__ __forceinline__ uint32_t smem_u32(const void* p) {
    uint32_t a;
    asm("{ .reg .u64 t; cvta.to.shared.u64 t, %1; cvt.u32.u64 %0, t; }" : "=r"(a) : "l"(p));
    return a;
}
__device__ __forceinline__ float tf32_rna(float x) {
    float y; asm("cvt.rna.tf32.f32 %0, %1;" : "=f"(y) : "f"(x)); return y;
}
__device__ __forceinline__ void cp16(uint32_t dst, const void* src) {
    asm volatile("cp.async.cg.shared.global [%0], [%1], 16;" :: "r"(dst), "l"(src) : "memory");
}
#define CP_COMMIT() asm volatile("cp.async.commit_group;" ::: "memory")
#define CP_WAIT1()  asm volatile("cp.async.wait_group 1;" ::: "memory")

__device__ __forceinline__ void ldsm4(uint32_t* r, uint32_t addr) {
    asm volatile("ldmatrix.sync.aligned.m8n8.x4.shared.b16 {%0,%1,%2,%3}, [%4];"
                 : "=r"(r[0]), "=r"(r[1]), "=r"(r[2]), "=r"(r[3]) : "r"(addr));
}
__device__ __forceinline__ void mma8(float* c, const uint32_t* a, uint32_t b0, uint32_t b1) {
    asm volatile("mma.sync.aligned.m16n8k8.row.col.f32.tf32.tf32.f32 "
                 "{%0,%1,%2,%3}, {%4,%5,%6,%7}, {%8,%9}, {%0,%1,%2,%3};"
                 : "+f"(c[0]), "+f"(c[1]), "+f"(c[2]), "+f"(c[3])
                 : "r"(a[0]), "r"(a[1]), "r"(a[2]), "r"(a[3]), "r"(b0), "r"(b1));
}
// swizzled byte offset for K-major tile, 128B rows: row r, 16B chunk c
__device__ __forceinline__ uint32_t swoff(int r, int c) {
    return (uint32_t)(r * 128 + ((c ^ (r & 7)) << 4));
}

// ---------------- prep kernel ----------------
__global__ void transpose_round_W(const float* __restrict__ W) {
    __shared__ float t[32][33];
    const int e = blockIdx.y;
    const int n0 = blockIdx.x * 32;
    const int tid = threadIdx.x;            // 256
    {
        const int i = tid >> 3, k4 = (tid & 7) * 4;
        float4 v = *(const float4*)(W + ((size_t)e * KR + n0 + i) * 32 + k4);
        t[i][k4 + 0] = tf32_rna(v.x);
        t[i][k4 + 1] = tf32_rna(v.y);
        t[i][k4 + 2] = tf32_rna(v.z);
        t[i][k4 + 3] = tf32_rna(v.w);
    }
    __syncthreads();
    {
        const int k = tid >> 3, j4 = (tid & 7) * 4;
        float4 o = make_float4(t[j4 + 0][k], t[j4 + 1][k], t[j4 + 2][k], t[j4 + 3][k]);
        *(float4*)(g_Bt + ((size_t)(e * 32 + k)) * KR + n0 + j4) = o;
    }
}

// ---------------- main GEMM ----------------
__global__ __launch_bounds__(256, 2)
void gemm_tf32_mma(const float* __restrict__ A, float* __restrict__ out) {
    extern __shared__ char smem[];
    const uint32_t sb = smem_u32(smem);
    const int tid  = threadIdx.x;
    const int lane = tid & 31;
    const int wid  = tid >> 5;
    const int warp_m = wid & 1;     // 2 warps over M  -> 64 rows each
    const int warp_n = wid >> 1;    // 4 warps over N  -> 32 cols each
    const int rowBase = blockIdx.y * BM;
    const int colBase = blockIdx.x * BN;

    const float* gA = A + (size_t)rowBase * KR;
    const float* gB = g_Bt + (size_t)colBase * KR;

    // ---- cp.async tile loader: 128 rows x 8 chunks each for A and B ----
    auto load_tile = [&](int stage, int kt) {
        const uint32_t abase = sb + stage * STAGE_BYTES;
        const uint32_t bbase = abase + A_STAGE;
        #pragma unroll
        for (int i = 0; i < 4; i++) {
            const int lin = i * 256 + tid;
            const int r = lin >> 3, c = lin & 7;
            cp16(abase + swoff(r, c), gA + (size_t)r * KR + kt * BK + c * 4);
        }
        #pragma unroll
        for (int i = 0; i < 4; i++) {
            const int lin = i * 256 + tid;
            const int r = lin >> 3, c = lin & 7;
            cp16(bbase + swoff(r, c), gB + (size_t)r * KR + kt * BK + c * 4);
        }
    };

    // ---- per-lane ldmatrix row offsets ----
    const int lrow  = ((lane >> 3) & 1) * 8 + (lane & 7);  // row within 16-row frag
    const int lxor  = lane & 7;                             // swizzle xor
    const int lhalf = lane >> 4;                            // chunk +0 / +1
    uint32_t aRow[4], bRow[2];
    #pragma unroll
    for (int mi = 0; mi < 4; mi++) aRow[mi] = (uint32_t)((warp_m * 64 + mi * 16 + lrow) * 128);
    #pragma unroll
    for (int nb = 0; nb < 2; nb++) bRow[nb] = (uint32_t)((warp_n * 32 + nb * 16 + lrow) * 128);

    float acc[4][4][4];
    #pragma unroll
    for (int mi = 0; mi < 4; mi++)
        #pragma unroll
        for (int ni = 0; ni < 4; ni++)
            #pragma unroll
            for (int q = 0; q < 4; q++) acc[mi][ni][q] = 0.0f;

    // ---- pipeline prologue: fill 2 stages ----
    load_tile(0, 0); CP_COMMIT();
    load_tile(1, 1); CP_COMMIT();

    for (int kt = 0; kt < KTILES; kt++) {
        CP_WAIT1();
        __syncthreads();

        // prefetch kt+2 (empty commit keeps group counting uniform)
        if (kt + 2 < KTILES) load_tile((kt + 2) % STAGES, kt + 2);
        CP_COMMIT();

        const uint32_t abase = sb + (kt % STAGES) * STAGE_BYTES;
        const uint32_t bbase = abase + A_STAGE;

        #pragma unroll
        for (int ks = 0; ks < 4; ks++) {
            const int chunk = ks * 2 + lhalf;
            const uint32_t coff = (uint32_t)((chunk ^ lxor) << 4);

            uint32_t a[4][4];
            #pragma unroll
            for (int mi = 0; mi < 4; mi++) ldsm4(a[mi], abase + aRow[mi] + coff);
            uint32_t b[2][4];
            #pragma unroll
            for (int nb = 0; nb < 2; nb++) ldsm4(b[nb], bbase + bRow[nb] + coff);

            #pragma unroll
            for (int mi = 0; mi < 4; mi++)
                #pragma unroll
                for (int nb = 0; nb < 2; nb++) {
                    mma8(acc[mi][nb * 2 + 0], a[mi], b[nb][0], b[nb][2]);
                    mma8(acc[mi][nb * 2 + 1], a[mi], b[nb][1], b[nb][3]);
                }
        }
    }

    // ---- epilogue: direct stores (float2 per frag row) ----
    const int g = lane >> 2, t = lane & 3;
    #pragma unroll
    for (int mi = 0; mi < 4; mi++) {
        const int r0 = rowBase + warp_m * 64 + mi * 16 + g;
        #pragma unroll
        for (int ni = 0; ni < 4; ni++) {
            const int col = colBase + warp_n * 32 + ni * 8 + t * 2;
            *(float2*)(out + (size_t)r0 * NOUT + col) =
                make_float2(acc[mi][ni][0], acc[mi][ni][1]);
            *(float2*)(out + (size_t)(r0 + 8) * NOUT + col) =
                make_float2(acc[mi][ni][2], acc[mi][ni][3]);
        }
    }
}

extern "C" void kernel_launch(void* const* d_in, const int* in_sizes, int n_in,
                              void* d_out, int out_size)
{
    const float* A = (const float*)d_in[0];
    const float* W = (const float*)d_in[1];
    float* out = (float*)d_out;

    cudaFuncSetAttribute(gemm_tf32_mma, cudaFuncAttributeMaxDynamicSharedMemorySize, SMEM_TOTAL);

    transpose_round_W<<<dim3(KR / 32, E_DIM), 256>>>(W);
    gemm_tf32_mma<<<dim3(NOUT / BN, M_DIM / BM), 256, SMEM_TOTAL>>>(A, out);
}

// round 6
// speedup vs baseline: 3.6516x; 1.0234x over previous
#include <cuda_runtime.h>
#include <cstdint>

// out[m, e*32+k] = sum_n A[m,n] * W[e,n,k]
// => C[8192,2048] = A[8192,1024] x B[1024,2048], B[n, e*32+k] = W[e,n,k]
// mma.sync.m16n8k8 tf32; 128x128 tiles, 3 stages, 2 CTAs/SM.
// R6: no modulo in hot loop, hoisted addressing, B-fragment software pipeline.

#define M_DIM 8192
#define KR    1024
#define NOUT  2048
#define E_DIM 64

#define BM 128
#define BN 128
#define BK 32
#define STAGES 3
#define KTILES (KR / BK)                 // 32

#define A_STAGE (BM * BK * 4)            // 16 KB
#define B_STAGE (BN * BK * 4)            // 16 KB
#define STAGE_BYTES (A_STAGE + B_STAGE)  // 32 KB
#define SMEM_TOTAL (STAGES * STAGE_BYTES)// 96 KB -> 2 CTAs/SM

__device__ float g_Bt[(size_t)NOUT * KR];    // 8 MB: W transposed+rounded, [col][n]

// ---------------- helpers ----------------
__device__ __forceinline__ uint32_t smem_u32(const void* p) {
    uint32_t a;
    asm("{ .reg .u64 t; cvta.to.shared.u64 t, %1; cvt.u32.u64 %0, t; }" : "=r"(a) : "l"(p));
    return a;
}
__device__ __forceinline__ float tf32_rna(float x) {
    float y; asm("cvt.rna.tf32.f32 %0, %1;" : "=f"(y) : "f"(x)); return y;
}
__device__ __forceinline__ void cp16(uint32_t dst, const void* src) {
    asm volatile("cp.async.cg.shared.global [%0], [%1], 16;" :: "r"(dst), "l"(src) : "memory");
}
#define CP_COMMIT() asm volatile("cp.async.commit_group;" ::: "memory")
#define CP_WAIT1()  asm volatile("cp.async.wait_group 1;" ::: "memory")

__device__ __forceinline__ void ldsm4(uint32_t* r, uint32_t addr) {
    asm volatile("ldmatrix.sync.aligned.m8n8.x4.shared.b16 {%0,%1,%2,%3}, [%4];"
                 : "=r"(r[0]), "=r"(r[1]), "=r"(r[2]), "=r"(r[3]) : "r"(addr));
}
__device__ __forceinline__ void mma8(float* c, const uint32_t* a, uint32_t b0, uint32_t b1) {
    asm volatile("mma.sync.aligned.m16n8k8.row.col.f32.tf32.tf32.f32 "
                 "{%0,%1,%2,%3}, {%4,%5,%6,%7}, {%8,%9}, {%0,%1,%2,%3};"
                 : "+f"(c[0]), "+f"(c[1]), "+f"(c[2]), "+f"(c[3])
                 : "r"(a[0]), "r"(a[1]), "r"(a[2]), "r"(a[3]), "r"(b0), "r"(b1));
}
// swizzled byte offset for K-major tile, 128B rows: row r, 16B chunk c
__device__ __forceinline__ uint32_t swoff(int r, int c) {
    return (uint32_t)(r * 128 + ((c ^ (r & 7)) << 4));
}

// ---------------- prep kernel ----------------
__global__ void transpose_round_W(const float* __restrict__ W) {
    __shared__ float t[32][33];
    const int e = blockIdx.y;
    const int n0 = blockIdx.x * 32;
    const int tid = threadIdx.x;            // 256
    {
        const int i = tid >> 3, k4 = (tid & 7) * 4;
        float4 v = *(const float4*)(W + ((size_t)e * KR + n0 + i) * 32 + k4);
        t[i][k4 + 0] = tf32_rna(v.x);
        t[i][k4 + 1] = tf32_rna(v.y);
        t[i][k4 + 2] = tf32_rna(v.z);
        t[i][k4 + 3] = tf32_rna(v.w);
    }
    __syncthreads();
    {
        const int k = tid >> 3, j4 = (tid & 7) * 4;
        float4 o = make_float4(t[j4 + 0][k], t[j4 + 1][k], t[j4 + 2][k], t[j4 + 3][k]);
        *(float4*)(g_Bt + ((size_t)(e * 32 + k)) * KR + n0 + j4) = o;
    }
}

// ---------------- main GEMM ----------------
__global__ __launch_bounds__(256, 2)
void gemm_tf32_mma(const float* __restrict__ A, float* __restrict__ out) {
    extern __shared__ char smem[];
    const uint32_t sb = smem_u32(smem);
    const int tid  = threadIdx.x;
    const int lane = tid & 31;
    const int wid  = tid >> 5;
    const int warp_m = wid & 1;     // 2 warps over M  -> 64 rows each
    const int warp_n = wid >> 1;    // 4 warps over N  -> 32 cols each
    const int rowBase = blockIdx.y * BM;
    const int colBase = blockIdx.x * BN;

    // ---- loop-invariant cp.async addressing ----
    const int ldr = tid >> 3;                 // 0..31
    const int ldc = tid & 7;                  // 16B chunk
    const float* aSrc = A    + ((size_t)rowBase + ldr) * KR + ldc * 4;
    const float* bSrc = g_Bt + ((size_t)colBase + ldr) * KR + ldc * 4;
    uint32_t aDst[4], bDst[4];
    #pragma unroll
    for (int i = 0; i < 4; i++) {
        aDst[i] = sb + swoff(ldr + i * 32, ldc);
        bDst[i] = sb + A_STAGE + swoff(ldr + i * 32, ldc);
    }

    // ---- loop-invariant ldsm addressing ----
    const int lrow  = ((lane >> 3) & 1) * 8 + (lane & 7);
    const int lxor  = lane & 7;
    const int lhalf = lane >> 4;
    uint32_t aBase[4], bBase[2], coff[4];
    #pragma unroll
    for (int mi = 0; mi < 4; mi++)
        aBase[mi] = sb + (uint32_t)((warp_m * 64 + mi * 16 + lrow) * 128);
    #pragma unroll
    for (int nb = 0; nb < 2; nb++)
        bBase[nb] = sb + A_STAGE + (uint32_t)((warp_n * 32 + nb * 16 + lrow) * 128);
    #pragma unroll
    for (int ks = 0; ks < 4; ks++)
        coff[ks] = (uint32_t)(((ks * 2 + lhalf) ^ lxor) << 4);

    float acc[4][4][4];
    #pragma unroll
    for (int mi = 0; mi < 4; mi++)
        #pragma unroll
        for (int ni = 0; ni < 4; ni++)
            #pragma unroll
            for (int q = 0; q < 4; q++) acc[mi][ni][q] = 0.0f;

    // ---- pipeline prologue: fill stages 0,1 ----
    #pragma unroll
    for (int i = 0; i < 4; i++) cp16(aDst[i], aSrc + (size_t)i * 32 * KR);
    #pragma unroll
    for (int i = 0; i < 4; i++) cp16(bDst[i], bSrc + (size_t)i * 32 * KR);
    CP_COMMIT();
    #pragma unroll
    for (int i = 0; i < 4; i++) cp16(aDst[i] + STAGE_BYTES, aSrc + (size_t)i * 32 * KR + BK);
    #pragma unroll
    for (int i = 0; i < 4; i++) cp16(bDst[i] + STAGE_BYTES, bSrc + (size_t)i * 32 * KR + BK);
    CP_COMMIT();

    uint32_t prod_off = 2 * STAGE_BYTES;   // stage receiving kt+2
    uint32_t cons_off = 0;                 // stage consumed at kt
    const float* aP = aSrc + 2 * BK;       // src for kt+2
    const float* bP = bSrc + 2 * BK;

    for (int kt = 0; kt < KTILES; kt++) {
        CP_WAIT1();
        __syncthreads();

        if (kt + 2 < KTILES) {
            #pragma unroll
            for (int i = 0; i < 4; i++) cp16(aDst[i] + prod_off, aP + (size_t)i * 32 * KR);
            #pragma unroll
            for (int i = 0; i < 4; i++) cp16(bDst[i] + prod_off, bP + (size_t)i * 32 * KR);
            aP += BK; bP += BK;
        }
        CP_COMMIT();
        prod_off += STAGE_BYTES;
        if (prod_off == STAGES * STAGE_BYTES) prod_off = 0;

        // ---- compute: B fragments pipelined one ks ahead ----
        uint32_t b_cur[2][4], b_nxt[2][4];
        ldsm4(b_cur[0], bBase[0] + cons_off + coff[0]);
        ldsm4(b_cur[1], bBase[1] + cons_off + coff[0]);

        #pragma unroll
        for (int ks = 0; ks < 4; ks++) {
            uint32_t a[4][4];
            #pragma unroll
            for (int mi = 0; mi < 4; mi++)
                ldsm4(a[mi], aBase[mi] + cons_off + coff[ks]);
            if (ks < 3) {
                ldsm4(b_nxt[0], bBase[0] + cons_off + coff[ks + 1]);
                ldsm4(b_nxt[1], bBase[1] + cons_off + coff[ks + 1]);
            }
            #pragma unroll
            for (int mi = 0; mi < 4; mi++)
                #pragma unroll
                for (int nb = 0; nb < 2; nb++) {
                    mma8(acc[mi][nb * 2 + 0], a[mi], b_cur[nb][0], b_cur[nb][2]);
                    mma8(acc[mi][nb * 2 + 1], a[mi], b_cur[nb][1], b_cur[nb][3]);
                }
            #pragma unroll
            for (int nb = 0; nb < 2; nb++)
                #pragma unroll
                for (int q = 0; q < 4; q++) b_cur[nb][q] = b_nxt[nb][q];
        }

        cons_off += STAGE_BYTES;
        if (cons_off == STAGES * STAGE_BYTES) cons_off = 0;
    }

    // ---- epilogue: direct stores (float2 per frag row) ----
    const int g = lane >> 2, t = lane & 3;
    #pragma unroll
    for (int mi = 0; mi < 4; mi++) {
        const int r0 = rowBase + warp_m * 64 + mi * 16 + g;
        #pragma unroll
        for (int ni = 0; ni < 4; ni++) {
            const int col = colBase + warp_n * 32 + ni * 8 + t * 2;
            *(float2*)(out + (size_t)r0 * NOUT + col) =
                make_float2(acc[mi][ni][0], acc[mi][ni][1]);
            *(float2*)(out + (size_t)(r0 + 8) * NOUT + col) =
                make_float2(acc[mi][ni][2], acc[mi][ni][3]);
        }
    }
}

extern "C" void kernel_launch(void* const* d_in, const int* in_sizes, int n_in,
                              void* d_out, int out_size)
{
    const float* A = (const float*)d_in[0];
    const float* W = (const float*)d_in[1];
    float* out = (float*)d_out;

    cudaFuncSetAttribute(gemm_tf32_mma, cudaFuncAttributeMaxDynamicSharedMemorySize, SMEM_TOTAL);

    transpose_round_W<<<dim3(KR / 32, E_DIM), 256>>>(W);
    gemm_tf32_mma<<<dim3(NOUT / BN, M_DIM / BM), 256, SMEM_TOTAL>>>(A, out);
}

// round 7
// speedup vs baseline: 3.7140x; 1.0171x over previous
#include <cuda_runtime.h>
#include <cstdint>

// out[m, e*32+k] = sum_n A[m,n] * W[e,n,k]
// => C[8192,2048] = A[8192,1024] x B[1024,2048], B[n, e*32+k] = W[e,n,k]
// mma.sync.m16n8k8 tf32; 128x128 CTA tile, 4 warps (64x64 warp tile),
// 3 stages, 2 CTAs/SM. R7: halved smem fragment traffic.

#define M_DIM 8192
#define KR    1024
#define NOUT  2048
#define E_DIM 64

#define BM 128
#define BN 128
#define BK 32
#define STAGES 3
#define KTILES (KR / BK)                 // 32

#define A_STAGE (BM * BK * 4)            // 16 KB
#define B_STAGE (BN * BK * 4)            // 16 KB
#define STAGE_BYTES (A_STAGE + B_STAGE)  // 32 KB
#define SMEM_TOTAL (STAGES * STAGE_BYTES)// 96 KB -> 2 CTAs/SM

__device__ float g_Bt[(size_t)NOUT * KR];    // 8 MB: W transposed+rounded, [col][n]

// ---------------- helpers ----------------
__device__ __forceinline__ uint32_t smem_u32(const void* p) {
    uint32_t a;
    asm("{ .reg .u64 t; cvta.to.shared.u64 t, %1; cvt.u32.u64 %0, t; }" : "=r"(a) : "l"(p));
    return a;
}
__device__ __forceinline__ float tf32_rna(float x) {
    float y; asm("cvt.rna.tf32.f32 %0, %1;" : "=f"(y) : "f"(x)); return y;
}
__device__ __forceinline__ void cp16(uint32_t dst, const void* src) {
    asm volatile("cp.async.cg.shared.global [%0], [%1], 16;" :: "r"(dst), "l"(src) : "memory");
}
#define CP_COMMIT() asm volatile("cp.async.commit_group;" ::: "memory")
#define CP_WAIT1()  asm volatile("cp.async.wait_group 1;" ::: "memory")

__device__ __forceinline__ void ldsm4(uint32_t* r, uint32_t addr) {
    asm volatile("ldmatrix.sync.aligned.m8n8.x4.shared.b16 {%0,%1,%2,%3}, [%4];"
                 : "=r"(r[0]), "=r"(r[1]), "=r"(r[2]), "=r"(r[3]) : "r"(addr));
}
__device__ __forceinline__ void mma8(float* c, const uint32_t* a, uint32_t b0, uint32_t b1) {
    asm volatile("mma.sync.aligned.m16n8k8.row.col.f32.tf32.tf32.f32 "
                 "{%0,%1,%2,%3}, {%4,%5,%6,%7}, {%8,%9}, {%0,%1,%2,%3};"
                 : "+f"(c[0]), "+f"(c[1]), "+f"(c[2]), "+f"(c[3])
                 : "r"(a[0]), "r"(a[1]), "r"(a[2]), "r"(a[3]), "r"(b0), "r"(b1));
}
// swizzled byte offset for K-major tile, 128B rows: row r, 16B chunk c
__device__ __forceinline__ uint32_t swoff(int r, int c) {
    return (uint32_t)(r * 128 + ((c ^ (r & 7)) << 4));
}

// ---------------- prep kernel ----------------
__global__ void transpose_round_W(const float* __restrict__ W) {
    __shared__ float t[32][33];
    const int e = blockIdx.y;
    const int n0 = blockIdx.x * 32;
    const int tid = threadIdx.x;            // 256
    {
        const int i = tid >> 3, k4 = (tid & 7) * 4;
        float4 v = *(const float4*)(W + ((size_t)e * KR + n0 + i) * 32 + k4);
        t[i][k4 + 0] = tf32_rna(v.x);
        t[i][k4 + 1] = tf32_rna(v.y);
        t[i][k4 + 2] = tf32_rna(v.z);
        t[i][k4 + 3] = tf32_rna(v.w);
    }
    __syncthreads();
    {
        const int k = tid >> 3, j4 = (tid & 7) * 4;
        float4 o = make_float4(t[j4 + 0][k], t[j4 + 1][k], t[j4 + 2][k], t[j4 + 3][k]);
        *(float4*)(g_Bt + ((size_t)(e * 32 + k)) * KR + n0 + j4) = o;
    }
}

// ---------------- main GEMM ----------------
__global__ __launch_bounds__(128, 2)
void gemm_tf32_mma(const float* __restrict__ A, float* __restrict__ out) {
    extern __shared__ char smem[];
    const uint32_t sb = smem_u32(smem);
    const int tid  = threadIdx.x;
    const int lane = tid & 31;
    const int wid  = tid >> 5;
    const int warp_m = wid & 1;     // 2 warps over M  -> 64 rows each
    const int warp_n = wid >> 1;    // 2 warps over N  -> 64 cols each
    const int rowBase = blockIdx.y * BM;
    const int colBase = blockIdx.x * BN;

    // ---- loop-invariant cp.async addressing ----
    // 128 threads: each covers rows ldr + 16*i, i=0..7 (one 16B chunk each)
    const int ldr = tid >> 3;                 // 0..15
    const int ldc = tid & 7;                  // 16B chunk
    const float* aSrc = A    + ((size_t)rowBase + ldr) * KR + ldc * 4;
    const float* bSrc = g_Bt + ((size_t)colBase + ldr) * KR + ldc * 4;
    const uint32_t aDst0 = sb + swoff(ldr, ldc);            // +2048*i for row+16i
    const uint32_t bDst0 = sb + A_STAGE + swoff(ldr, ldc);

    // ---- loop-invariant ldsm addressing ----
    const int lrow  = ((lane >> 3) & 1) * 8 + (lane & 7);
    const int lxor  = lane & 7;
    const int lhalf = lane >> 4;
    const uint32_t aBase = sb + (uint32_t)((warp_m * 64 + lrow) * 128);
    const uint32_t bBase = sb + A_STAGE + (uint32_t)((warp_n * 64 + lrow) * 128);
    uint32_t coff[4];
    #pragma unroll
    for (int ks = 0; ks < 4; ks++)
        coff[ks] = (uint32_t)(((ks * 2 + lhalf) ^ lxor) << 4);

    float acc[4][8][4];
    #pragma unroll
    for (int mi = 0; mi < 4; mi++)
        #pragma unroll
        for (int ni = 0; ni < 8; ni++)
            #pragma unroll
            for (int q = 0; q < 4; q++) acc[mi][ni][q] = 0.0f;

    // ---- pipeline prologue: fill stages 0,1 ----
    #pragma unroll
    for (int i = 0; i < 8; i++) cp16(aDst0 + i * 2048u, aSrc + (size_t)i * 16 * KR);
    #pragma unroll
    for (int i = 0; i < 8; i++) cp16(bDst0 + i * 2048u, bSrc + (size_t)i * 16 * KR);
    CP_COMMIT();
    #pragma unroll
    for (int i = 0; i < 8; i++) cp16(aDst0 + STAGE_BYTES + i * 2048u, aSrc + (size_t)i * 16 * KR + BK);
    #pragma unroll
    for (int i = 0; i < 8; i++) cp16(bDst0 + STAGE_BYTES + i * 2048u, bSrc + (size_t)i * 16 * KR + BK);
    CP_COMMIT();

    uint32_t prod_off = 2 * STAGE_BYTES;   // stage receiving kt+2
    uint32_t cons_off = 0;                 // stage consumed at kt
    const float* aP = aSrc + 2 * BK;
    const float* bP = bSrc + 2 * BK;

    for (int kt = 0; kt < KTILES; kt++) {
        CP_WAIT1();
        __syncthreads();

        if (kt + 2 < KTILES) {
            #pragma unroll
            for (int i = 0; i < 8; i++) cp16(aDst0 + prod_off + i * 2048u, aP + (size_t)i * 16 * KR);
            #pragma unroll
            for (int i = 0; i < 8; i++) cp16(bDst0 + prod_off + i * 2048u, bP + (size_t)i * 16 * KR);
            aP += BK; bP += BK;
        }
        CP_COMMIT();
        prod_off += STAGE_BYTES;
        if (prod_off == STAGES * STAGE_BYTES) prod_off = 0;

        // ---- compute: B fragments pipelined one ks ahead ----
        uint32_t b_cur[4][4], b_nxt[4][4];
        #pragma unroll
        for (int nb = 0; nb < 4; nb++)
            ldsm4(b_cur[nb], bBase + cons_off + nb * 2048u + coff[0]);

        #pragma unroll
        for (int ks = 0; ks < 4; ks++) {
            uint32_t a[4][4];
            #pragma unroll
            for (int mi = 0; mi < 4; mi++)
                ldsm4(a[mi], aBase + cons_off + mi * 2048u + coff[ks]);
            if (ks < 3) {
                #pragma unroll
                for (int nb = 0; nb < 4; nb++)
                    ldsm4(b_nxt[nb], bBase + cons_off + nb * 2048u + coff[ks + 1]);
            }
            #pragma unroll
            for (int mi = 0; mi < 4; mi++)
                #pragma unroll
                for (int nb = 0; nb < 4; nb++) {
                    mma8(acc[mi][nb * 2 + 0], a[mi], b_cur[nb][0], b_cur[nb][2]);
                    mma8(acc[mi][nb * 2 + 1], a[mi], b_cur[nb][1], b_cur[nb][3]);
                }
            #pragma unroll
            for (int nb = 0; nb < 4; nb++)
                #pragma unroll
                for (int q = 0; q < 4; q++) b_cur[nb][q] = b_nxt[nb][q];
        }

        cons_off += STAGE_BYTES;
        if (cons_off == STAGES * STAGE_BYTES) cons_off = 0;
    }

    // ---- epilogue: direct stores (float2 per frag row) ----
    const int g = lane >> 2, t = lane & 3;
    #pragma unroll
    for (int mi = 0; mi < 4; mi++) {
        const int r0 = rowBase + warp_m * 64 + mi * 16 + g;
        #pragma unroll
        for (int ni = 0; ni < 8; ni++) {
            const int col = colBase + warp_n * 64 + ni * 8 + t * 2;
            *(float2*)(out + (size_t)r0 * NOUT + col) =
                make_float2(acc[mi][ni][0], acc[mi][ni][1]);
            *(float2*)(out + (size_t)(r0 + 8) * NOUT + col) =
                make_float2(acc[mi][ni][2], acc[mi][ni][3]);
        }
    }
}

extern "C" void kernel_launch(void* const* d_in, const int* in_sizes, int n_in,
                              void* d_out, int out_size)
{
    const float* A = (const float*)d_in[0];
    const float* W = (const float*)d_in[1];
    float* out = (float*)d_out;

    cudaFuncSetAttribute(gemm_tf32_mma, cudaFuncAttributeMaxDynamicSharedMemorySize, SMEM_TOTAL);

    transpose_round_W<<<dim3(KR / 32, E_DIM), 256>>>(W);
    gemm_tf32_mma<<<dim3(NOUT / BN, M_DIM / BM), 128, SMEM_TOTAL>>>(A, out);
}

// round 8
// speedup vs baseline: 4.2995x; 1.1576x over previous
#include <cuda_runtime.h>
#include <cstdint>

// out[m, e*32+k] = sum_n A[m,n] * W[e,n,k]
// => C[8192,2048] = A[8192,1024] x B[1024,2048], B[n, e*32+k] = W[e,n,k]
// mma.sync.m16n8k8 tf32; 128x128 CTA tile, 4 warps (64x64), 3 stages, 2 CTAs/SM.
// R8: parity-double-buffered fragments, cross-kt fragment preload,
//     wait+barrier buried mid-loop so each kt starts with immediate MMAs.

#define M_DIM 8192
#define KR    1024
#define NOUT  2048
#define E_DIM 64

#define BM 128
#define BN 128
#define BK 32
#define STAGES 3
#define KTILES (KR / BK)                 // 32

#define A_STAGE (BM * BK * 4)            // 16 KB
#define B_STAGE (BN * BK * 4)            // 16 KB
#define STAGE_BYTES (A_STAGE + B_STAGE)  // 32 KB
#define SMEM_TOTAL (STAGES * STAGE_BYTES)// 96 KB -> 2 CTAs/SM

__device__ float g_Bt[(size_t)NOUT * KR];    // 8 MB: W transposed+rounded, [col][n]

// ---------------- helpers ----------------
__device__ __forceinline__ uint32_t smem_u32(const void* p) {
    uint32_t a;
    asm("{ .reg .u64 t; cvta.to.shared.u64 t, %1; cvt.u32.u64 %0, t; }" : "=r"(a) : "l"(p));
    return a;
}
__device__ __forceinline__ float tf32_rna(float x) {
    float y; asm("cvt.rna.tf32.f32 %0, %1;" : "=f"(y) : "f"(x)); return y;
}
__device__ __forceinline__ void cp16(uint32_t dst, const void* src) {
    asm volatile("cp.async.cg.shared.global [%0], [%1], 16;" :: "r"(dst), "l"(src) : "memory");
}
#define CP_COMMIT() asm volatile("cp.async.commit_group;" ::: "memory")
#define CP_WAIT0()  asm volatile("cp.async.wait_group 0;" ::: "memory")
#define CP_WAIT1()  asm volatile("cp.async.wait_group 1;" ::: "memory")

__device__ __forceinline__ void ldsm4(uint32_t* r, uint32_t addr) {
    asm volatile("ldmatrix.sync.aligned.m8n8.x4.shared.b16 {%0,%1,%2,%3}, [%4];"
                 : "=r"(r[0]), "=r"(r[1]), "=r"(r[2]), "=r"(r[3]) : "r"(addr));
}
__device__ __forceinline__ void mma8(float* c, const uint32_t* a, uint32_t b0, uint32_t b1) {
    asm volatile("mma.sync.aligned.m16n8k8.row.col.f32.tf32.tf32.f32 "
                 "{%0,%1,%2,%3}, {%4,%5,%6,%7}, {%8,%9}, {%0,%1,%2,%3};"
                 : "+f"(c[0]), "+f"(c[1]), "+f"(c[2]), "+f"(c[3])
                 : "r"(a[0]), "r"(a[1]), "r"(a[2]), "r"(a[3]), "r"(b0), "r"(b1));
}
// swizzled byte offset for K-major tile, 128B rows: row r, 16B chunk c
__device__ __forceinline__ uint32_t swoff(int r, int c) {
    return (uint32_t)(r * 128 + ((c ^ (r & 7)) << 4));
}

// ---------------- prep kernel ----------------
__global__ void transpose_round_W(const float* __restrict__ W) {
    __shared__ float t[32][33];
    const int e = blockIdx.y;
    const int n0 = blockIdx.x * 32;
    const int tid = threadIdx.x;            // 256
    {
        const int i = tid >> 3, k4 = (tid & 7) * 4;
        float4 v = *(const float4*)(W + ((size_t)e * KR + n0 + i) * 32 + k4);
        t[i][k4 + 0] = tf32_rna(v.x);
        t[i][k4 + 1] = tf32_rna(v.y);
        t[i][k4 + 2] = tf32_rna(v.z);
        t[i][k4 + 3] = tf32_rna(v.w);
    }
    __syncthreads();
    {
        const int k = tid >> 3, j4 = (tid & 7) * 4;
        float4 o = make_float4(t[j4 + 0][k], t[j4 + 1][k], t[j4 + 2][k], t[j4 + 3][k]);
        *(float4*)(g_Bt + ((size_t)(e * 32 + k)) * KR + n0 + j4) = o;
    }
}

// ---------------- main GEMM ----------------
__global__ __launch_bounds__(128, 2)
void gemm_tf32_mma(const float* __restrict__ A, float* __restrict__ out) {
    extern __shared__ char smem[];
    const uint32_t sb = smem_u32(smem);
    const int tid  = threadIdx.x;
    const int lane = tid & 31;
    const int wid  = tid >> 5;
    const int warp_m = wid & 1;     // 2 warps over M  -> 64 rows each
    const int warp_n = wid >> 1;    // 2 warps over N  -> 64 cols each
    const int rowBase = blockIdx.y * BM;
    const int colBase = blockIdx.x * BN;

    // ---- loop-invariant cp.async addressing ----
    const int ldr = tid >> 3;                 // 0..15
    const int ldc = tid & 7;                  // 16B chunk
    const float* aSrc = A    + ((size_t)rowBase + ldr) * KR + ldc * 4;
    const float* bSrc = g_Bt + ((size_t)colBase + ldr) * KR + ldc * 4;
    const uint32_t aDst0 = sb + swoff(ldr, ldc);            // +2048*i for row+16i
    const uint32_t bDst0 = sb + A_STAGE + swoff(ldr, ldc);

    // ---- loop-invariant ldsm addressing ----
    const int lrow  = ((lane >> 3) & 1) * 8 + (lane & 7);
    const int lxor  = lane & 7;
    const int lhalf = lane >> 4;
    const uint32_t aBase = sb + (uint32_t)((warp_m * 64 + lrow) * 128);
    const uint32_t bBase = sb + A_STAGE + (uint32_t)((warp_n * 64 + lrow) * 128);
    uint32_t coff[4];
    #pragma unroll
    for (int ks = 0; ks < 4; ks++)
        coff[ks] = (uint32_t)(((ks * 2 + lhalf) ^ lxor) << 4);

    float acc[4][8][4];
    #pragma unroll
    for (int mi = 0; mi < 4; mi++)
        #pragma unroll
        for (int ni = 0; ni < 8; ni++)
            #pragma unroll
            for (int q = 0; q < 4; q++) acc[mi][ni][q] = 0.0f;

    // ---- fragment buffers (parity double-buffered, static indices) ----
    uint32_t a0[4][4], a1[4][4], b0[4][4], b1[4][4];

#define LDFRAG0(soff, ks) do { \
    _Pragma("unroll") for (int mi = 0; mi < 4; mi++) \
        ldsm4(a0[mi], aBase + (soff) + mi * 2048u + coff[ks]); \
    _Pragma("unroll") for (int nb = 0; nb < 4; nb++) \
        ldsm4(b0[nb], bBase + (soff) + nb * 2048u + coff[ks]); \
} while (0)
#define LDFRAG1(soff, ks) do { \
    _Pragma("unroll") for (int mi = 0; mi < 4; mi++) \
        ldsm4(a1[mi], aBase + (soff) + mi * 2048u + coff[ks]); \
    _Pragma("unroll") for (int nb = 0; nb < 4; nb++) \
        ldsm4(b1[nb], bBase + (soff) + nb * 2048u + coff[ks]); \
} while (0)
#define MMA_BURST(ab, bb) do { \
    _Pragma("unroll") for (int mi = 0; mi < 4; mi++) \
        _Pragma("unroll") for (int nb = 0; nb < 4; nb++) { \
            mma8(acc[mi][nb * 2 + 0], ab[mi], bb[nb][0], bb[nb][2]); \
            mma8(acc[mi][nb * 2 + 1], ab[mi], bb[nb][1], bb[nb][3]); \
        } \
} while (0)

    // ---- producer: issue one stage's cp.asyncs ----
#define ISSUE_STAGE(soff, aP, bP) do { \
    _Pragma("unroll") for (int i = 0; i < 8; i++) \
        cp16(aDst0 + (soff) + i * 2048u, (aP) + (size_t)i * 16 * KR); \
    _Pragma("unroll") for (int i = 0; i < 8; i++) \
        cp16(bDst0 + (soff) + i * 2048u, (bP) + (size_t)i * 16 * KR); \
} while (0)

    // ---- prologue: stages 0,1 in flight; wait s0; preload ks0 frags ----
    ISSUE_STAGE(0, aSrc, bSrc); CP_COMMIT();
    ISSUE_STAGE(STAGE_BYTES, aSrc + BK, bSrc + BK); CP_COMMIT();
    CP_WAIT1();
    __syncthreads();
    LDFRAG0(0, 0);

    uint32_t cons_off = 0;
    uint32_t prod_off = 2 * STAGE_BYTES;
    const float* aP = aSrc + 2 * BK;
    const float* bP = bSrc + 2 * BK;

    for (int kt = 0; kt < KTILES; kt++) {
        const uint32_t cur = cons_off;
        const uint32_t nxt = (cur + STAGE_BYTES == STAGES * STAGE_BYTES) ? 0u : cur + STAGE_BYTES;

        // ks0: frags in buf0; preload ks1 -> buf1
        LDFRAG1(cur, 1);
        MMA_BURST(a0, b0);
        // ks1: preload ks2 -> buf0
        LDFRAG0(cur, 2);
        MMA_BURST(a1, b1);
        // ks2: wait next stage's data, preload ks3 -> buf1
        CP_WAIT0();
        LDFRAG1(cur, 3);
        MMA_BURST(a0, b0);
        // barrier: (a) all warps see stage kt+1 (cp.async drained for whole CTA)
        //          (b) safe to overwrite stage kt-1 (= stage kt+2 slot)
        __syncthreads();
        // ks3: preload next kt's ks0 -> buf0; issue cp for kt+2; mma burst
        if (kt + 1 < KTILES) LDFRAG0(nxt, 0);
        if (kt + 2 < KTILES) {
            ISSUE_STAGE(prod_off, aP, bP);
            CP_COMMIT();
            aP += BK; bP += BK;
        }
        MMA_BURST(a1, b1);

        cons_off = nxt;
        prod_off = (prod_off + STAGE_BYTES == STAGES * STAGE_BYTES) ? 0u : prod_off + STAGE_BYTES;
    }

    // ---- epilogue: direct stores (float2 per frag row) ----
    const int g = lane >> 2, t = lane & 3;
    #pragma unroll
    for (int mi = 0; mi < 4; mi++) {
        const int r0 = rowBase + warp_m * 64 + mi * 16 + g;
        #pragma unroll
        for (int ni = 0; ni < 8; ni++) {
            const int col = colBase + warp_n * 64 + ni * 8 + t * 2;
            *(float2*)(out + (size_t)r0 * NOUT + col) =
                make_float2(acc[mi][ni][0], acc[mi][ni][1]);
            *(float2*)(out + (size_t)(r0 + 8) * NOUT + col) =
                make_float2(acc[mi][ni][2], acc[mi][ni][3]);
        }
    }
}

extern "C" void kernel_launch(void* const* d_in, const int* in_sizes, int n_in,
                              void* d_out, int out_size)
{
    const float* A = (const float*)d_in[0];
    const float* W = (const float*)d_in[1];
    float* out = (float*)d_out;

    cudaFuncSetAttribute(gemm_tf32_mma, cudaFuncAttributeMaxDynamicSharedMemorySize, SMEM_TOTAL);

    transpose_round_W<<<dim3(KR / 32, E_DIM), 256>>>(W);
    gemm_tf32_mma<<<dim3(NOUT / BN, M_DIM / BM), 128, SMEM_TOTAL>>>(A, out);
}